// round 9
// baseline (speedup 1.0000x reference)
#include <cuda_runtime.h>
#include <cuda_fp16.h>
#include <cstdint>

#define LL      8192
#define BATCH   32
#define NF      128
#define NT      128
#define NCTA    148
#define NITEMS  (BATCH*64)    // 2048 items; item = b*64 + u, u = k128 slab
#define NTH     512

// ---- global tables / scratch ----
__device__ __align__(16) __half g_C[LL*NF];          // [u][f][128k] 32KB tiles
__device__ __align__(16) __half g_Wh[NT*LL];         // [t][l] fp16
__device__ __align__(16) __half g_sigh[BATCH*LL];    // fp16 signal
__device__ __align__(16) float  g_part[NCTA*2*NF*NT];// 19.4MB partial segments

// ---- smem: rows padded to 272B (128k halfs + 16B) => conflict-free ldsm ----
#define ROWB     272
#define TILEB    (128*ROWB)                // 34816
#define OFF_A(buf)  ((buf)*TILEB)
#define OFF_B(buf)  (2*TILEB + (buf)*TILEB)
#define SMEM_DYN    (4*TILEB)              // 139264

// ---- PTX helpers ----
__device__ __forceinline__ uint32_t smem_u32(const void* p) {
    uint32_t a;
    asm("{ .reg .u64 t; cvta.to.shared.u64 t, %1; cvt.u32.u64 %0, t; }" : "=r"(a) : "l"(p));
    return a;
}
__device__ __forceinline__ void cpa16(uint32_t dst, const void* src) {
    asm volatile("cp.async.ca.shared.global [%0], [%1], 16;" :: "r"(dst), "l"(src));
}
#define CP_COMMIT() asm volatile("cp.async.commit_group;" ::: "memory")
#define CP_WAIT0()  asm volatile("cp.async.wait_group 0;" ::: "memory")

__device__ __forceinline__ void ldsm4(uint32_t r[4], uint32_t addr) {
    asm volatile("ldmatrix.sync.aligned.m8n8.x4.shared.b16 {%0,%1,%2,%3}, [%4];"
                 : "=r"(r[0]), "=r"(r[1]), "=r"(r[2]), "=r"(r[3]) : "r"(addr));
}
__device__ __forceinline__ void mma16816(float c[4], const uint32_t a[4],
                                         uint32_t b0, uint32_t b1) {
    asm volatile("mma.sync.aligned.m16n8k16.row.col.f32.f16.f16.f32 "
                 "{%0,%1,%2,%3}, {%4,%5,%6,%7}, {%8,%9}, {%0,%1,%2,%3};"
                 : "+f"(c[0]), "+f"(c[1]), "+f"(c[2]), "+f"(c[3])
                 : "r"(a[0]), "r"(a[1]), "r"(a[2]), "r"(a[3]), "r"(b0), "r"(b1));
}
__device__ __forceinline__ uint32_t hm2(uint32_t a, uint32_t b) {
    __half2 r = __hmul2(*(__half2*)&a, *(__half2*)&b);
    return *(uint32_t*)&r;
}

// ---------------------------------------------------------------------------
// Tables: C fp16 in [u][f][128k] tiles (exact fp32-phase replication),
// W fp16 [t][l], signal fp16.
// ---------------------------------------------------------------------------
__global__ void prep_tables(const float* __restrict__ sig) {
    int idx = blockIdx.x * blockDim.x + threadIdx.x;
    const int totC = LL * NF;
    if (idx < totC) {
        int u = idx >> 14;
        int r = idx & 16383;
        int f = r >> 7;
        int c = r & 127;
        int l = u * 128 + c;
        int fi = (f * 4096) / 127;
        float fv = (float)fi, lf = (float)l;
        const float TP = 6.2831854820251465f;
        const float DD = 1.7484556e-7f;
        float a  = TP * fv;
        float e1 = fmaf(TP, fv, -a);
        float bb = a * lf;
        float e2 = fmaf(a, lf, -bb);
        float eps = (DD * (fv * lf) - e1 * lf - e2) * (1.0f / 8192.0f);
        int m = (fi * l) & (LL - 1);
        float x = (float)m * (1.0f / 4096.0f);
        float s, cc;
        sincospif(x, &s, &cc);
        g_C[idx] = __float2half_rn(cc - eps * s);
    } else if (idx < 2 * totC) {
        int j = idx - totC;
        int t = j >> 13;
        int l = j & 8191;
        int tci = (t * 8191) / 127;
        float diff = (float)l - (float)tci;
        float x = diff / 819.2f;
        g_Wh[j] = __float2half_rn(expf(-0.5f * (x * x)));
    } else if (idx < 2 * totC + BATCH * LL) {
        int j = idx - 2 * totC;
        g_sigh[j] = __float2half_rn(sig[j]);
    }
}

// ---------------------------------------------------------------------------
// Persistent balanced GEMM. 148 CTAs x 512 thr. CTA c owns items
// [c*2048/148, (c+1)*2048/148); item = b*64+u computes the k-slab
// [u*128, u*128+128) contribution to batch b's 128x128 output.
// Segments (<=2 per CTA since runs are <64 items) flushed to g_part[c][seg].
// ---------------------------------------------------------------------------
__global__ void __launch_bounds__(NTH, 1)
gabor_mma() {
    extern __shared__ __align__(16) char smc[];
    const uint32_t smb = smem_u32(smc);
    const int tid = threadIdx.x, lane = tid & 31, wid = tid >> 5;
    const int c = blockIdx.x;
    const int start = c * NITEMS / NCTA;
    const int end   = (c + 1) * NITEMS / NCTA;
    const int bfirst = start >> 6;

    auto copyA = [&](int item, int buf) {
        const int u = item & 63;
        const char* src = (const char*)g_C + (size_t)u * 32768;
        const uint32_t dh = smb + OFF_A(buf);
#pragma unroll
        for (int r = 0; r < 4; r++) {
            int j = tid + NTH * r;               // 0..2047 16B chunks
            uint32_t doff = (uint32_t)(j >> 4) * ROWB + (j & 15) * 16;
            cpa16(dh + doff, src + j * 16);
        }
    };

    const int tp = tid >> 2, qq = tid & 3;       // row t, quarter (32 halfs each)
    auto buildP = [&](int item, int buf) {
        const int b = item >> 6, u = item & 63;
        const uint4* wp = (const uint4*)(g_Wh + (size_t)tp * LL + u * 128 + qq * 32);
        const uint4* sp = (const uint4*)(g_sigh + (size_t)b * LL + u * 128 + qq * 32);
        char* ph = smc + OFF_B(buf) + tp * ROWB + qq * 64;
#pragma unroll
        for (int m = 0; m < 4; m++) {
            uint4 w = wp[m], s = sp[m], p;
            p.x = hm2(w.x, s.x); p.y = hm2(w.y, s.y);
            p.z = hm2(w.z, s.z); p.w = hm2(w.w, s.w);
            *(uint4*)(ph + 16 * m) = p;
        }
    };

    copyA(start, 0); CP_COMMIT();
    buildP(start, 0);

    float acc[2][4][4];
#pragma unroll
    for (int m = 0; m < 2; m++)
#pragma unroll
        for (int n = 0; n < 4; n++)
#pragma unroll
            for (int q = 0; q < 4; q++) acc[m][n][q] = 0.0f;

    const int f0 = (wid & 3) * 32, t0 = (wid >> 2) * 32;
    const uint32_t loff = (uint32_t)(lane & 15) * ROWB + (lane >> 4) * 16;
    const int r0 = lane >> 2, c0 = (lane & 3) * 2;

    for (int it = start; it < end; it++) {
        CP_WAIT0();
        __syncthreads();
        const int buf = (it - start) & 1;
        if (it + 1 < end) {
            copyA(it + 1, buf ^ 1); CP_COMMIT();
            buildP(it + 1, buf ^ 1);
        }
        const uint32_t aH = smb + OFF_A(buf) + f0 * ROWB + loff;
        const uint32_t bH = smb + OFF_B(buf) + t0 * ROWB + loff;
#pragma unroll
        for (int k16 = 0; k16 < 8; k16++) {
            const uint32_t kb = k16 * 32;
            uint32_t ah[2][4], bh[2][4];
            ldsm4(ah[0], aH + kb); ldsm4(ah[1], aH + 16 * ROWB + kb);
            ldsm4(bh[0], bH + kb); ldsm4(bh[1], bH + 16 * ROWB + kb);
#pragma unroll
            for (int m = 0; m < 2; m++)
#pragma unroll
                for (int j = 0; j < 2; j++) {
                    mma16816(acc[m][2 * j],     ah[m], bh[j][0], bh[j][2]);
                    mma16816(acc[m][2 * j + 1], ah[m], bh[j][1], bh[j][3]);
                }
        }

        // segment flush when batch changes or run ends
        const int bcur = it >> 6;
        if (it + 1 == end || ((it + 1) >> 6) != bcur) {
            float* dst = g_part + ((size_t)c * 2 + (bcur - bfirst)) * (NF * NT);
#pragma unroll
            for (int m = 0; m < 2; m++)
#pragma unroll
                for (int n = 0; n < 4; n++) {
                    const int f = f0 + 16 * m + r0;
                    const int t = t0 + 16 * (n >> 1) + 8 * (n & 1) + c0;
                    *(float2*)&dst[f * NT + t]       = make_float2(acc[m][n][0], acc[m][n][1]);
                    *(float2*)&dst[(f + 8) * NT + t] = make_float2(acc[m][n][2], acc[m][n][3]);
                }
            if (it + 1 < end) {
#pragma unroll
                for (int m = 0; m < 2; m++)
#pragma unroll
                    for (int n = 0; n < 4; n++)
#pragma unroll
                        for (int q = 0; q < 4; q++) acc[m][n][q] = 0.0f;
            }
        }
    }
}

// ---------------------------------------------------------------------------
// Deterministic reduce: for each output element of batch b, sum segments from
// the <=9 candidate CTAs whose runs intersect [b*64, (b+1)*64).
// ---------------------------------------------------------------------------
__global__ void reduce_out(float* __restrict__ out) {
    int i = blockIdx.x * blockDim.x + threadIdx.x;   // float4 index
    const int n4 = BATCH * NF * NT / 4;              // 131072
    if (i >= n4) return;
    const int b = i >> 12;                           // 4096 float4 per batch
    const int e = i & 4095;
    float4 a = make_float4(0.f, 0.f, 0.f, 0.f);
    int cg = (b * 37) >> 3;                          // ~ b*4.625
    int clo = cg > 0 ? cg - 1 : 0;
    int chi = clo + 8; if (chi > NCTA - 1) chi = NCTA - 1;
    for (int c = clo; c <= chi; c++) {
        int sc = c * NITEMS / NCTA, ec = (c + 1) * NITEMS / NCTA;
        if (sc < (b + 1) * 64 && ec > b * 64) {
            int seg = b - (sc >> 6);
            const float4* p = (const float4*)g_part + ((size_t)c * 2 + seg) * 4096 + e;
            float4 v = *p;
            a.x += v.x; a.y += v.y; a.z += v.z; a.w += v.w;
        }
    }
    ((float4*)out)[i] = a;
}

extern "C" void kernel_launch(void* const* d_in, const int* in_sizes, int n_in,
                              void* d_out, int out_size) {
    const float* sig = (const float*)d_in[0];
    float* out = (float*)d_out;

    int ptot = 2 * LL * 128 + BATCH * LL;
    prep_tables<<<(ptot + 255) / 256, 256>>>(sig);

    cudaFuncSetAttribute(gabor_mma, cudaFuncAttributeMaxDynamicSharedMemorySize, SMEM_DYN);
    gabor_mma<<<NCTA, NTH, SMEM_DYN>>>();

    reduce_out<<<(BATCH * NF * NT / 4 + 255) / 256, 256>>>(out);
}

// round 10
// speedup vs baseline: 1.2078x; 1.2078x over previous
#include <cuda_runtime.h>
#include <cuda_fp16.h>
#include <cstdint>

#define LL      8192
#define BATCH   32
#define NF      128
#define NT      128
#define NCTA    296
#define NITEMS  (BATCH*128)   // 4096 items; item = b*128 + u, u = k64 slab
#define NTH     256

// ---- global tables / scratch ----
__device__ __align__(16) __half g_C[LL*NF];          // [u][f][64k] 16KB tiles
__device__ __align__(16) __half g_Wh[NT*LL];         // [t][l] fp16
__device__ __align__(16) __half g_sigh[BATCH*LL];    // fp16 signal
__device__ __align__(16) float  g_part[NCTA*2*NF*NT];// 38.8MB partial segments

// ---- smem: rows padded to 144B (64k halfs + 16B) => conflict-free ldsm ----
#define ROWB     144
#define TILEB    (128*ROWB)                // 18432
#define OFF_A(buf)  ((buf)*TILEB)
#define OFF_B(buf)  (2*TILEB + (buf)*TILEB)
#define SMEM_DYN    (4*TILEB)              // 73728 -> 2 CTAs/SM

// ---- PTX helpers ----
__device__ __forceinline__ uint32_t smem_u32(const void* p) {
    uint32_t a;
    asm("{ .reg .u64 t; cvta.to.shared.u64 t, %1; cvt.u32.u64 %0, t; }" : "=r"(a) : "l"(p));
    return a;
}
__device__ __forceinline__ void cpa16(uint32_t dst, const void* src) {
    asm volatile("cp.async.ca.shared.global [%0], [%1], 16;" :: "r"(dst), "l"(src));
}
#define CP_COMMIT() asm volatile("cp.async.commit_group;" ::: "memory")
#define CP_WAIT0()  asm volatile("cp.async.wait_group 0;" ::: "memory")

__device__ __forceinline__ void ldsm4(uint32_t r[4], uint32_t addr) {
    asm volatile("ldmatrix.sync.aligned.m8n8.x4.shared.b16 {%0,%1,%2,%3}, [%4];"
                 : "=r"(r[0]), "=r"(r[1]), "=r"(r[2]), "=r"(r[3]) : "r"(addr));
}
__device__ __forceinline__ void mma16816(float c[4], const uint32_t a[4],
                                         uint32_t b0, uint32_t b1) {
    asm volatile("mma.sync.aligned.m16n8k16.row.col.f32.f16.f16.f32 "
                 "{%0,%1,%2,%3}, {%4,%5,%6,%7}, {%8,%9}, {%0,%1,%2,%3};"
                 : "+f"(c[0]), "+f"(c[1]), "+f"(c[2]), "+f"(c[3])
                 : "r"(a[0]), "r"(a[1]), "r"(a[2]), "r"(a[3]), "r"(b0), "r"(b1));
}
__device__ __forceinline__ uint32_t hm2(uint32_t a, uint32_t b) {
    __half2 r = __hmul2(*(__half2*)&a, *(__half2*)&b);
    return *(uint32_t*)&r;
}

// ---------------------------------------------------------------------------
// Tables, 4 elements per thread (shared subexpressions, vector stores).
// C fp16 [u][f][64k] tiles, exact fp32-phase replication; W fp16 [t][l]; sig fp16.
// ---------------------------------------------------------------------------
__global__ void prep_tables(const float* __restrict__ sig) {
    int q = blockIdx.x * blockDim.x + threadIdx.x;
    const int nC = LL * NF / 4;           // 262144
    const int nW = NT * LL / 4;           // 262144
    if (q < nC) {
        int base = q * 4;
        int u = base >> 13;               // tile (l/64)
        int r = base & 8191;
        int f = r >> 6;
        int c = r & 63;                   // multiple of 4
        int fi = (f * 4096) / 127;
        float fv = (float)fi;
        const float TP = 6.2831854820251465f;
        const float DD = 1.7484556e-7f;
        float a  = TP * fv;
        float e1 = fmaf(TP, fv, -a);
        __half h[4];
#pragma unroll
        for (int i = 0; i < 4; i++) {
            int l = u * 64 + c + i;
            float lf = (float)l;
            float bb = a * lf;
            float e2 = fmaf(a, lf, -bb);
            float eps = (DD * (fv * lf) - e1 * lf - e2) * (1.0f / 8192.0f);
            int m = (fi * l) & (LL - 1);
            float x = (float)m * (1.0f / 4096.0f);
            float s, cc;
            sincospif(x, &s, &cc);
            h[i] = __float2half_rn(cc - eps * s);
        }
        *(uint2*)&g_C[base] = *(uint2*)h;
    } else if (q < nC + nW) {
        int base = (q - nC) * 4;
        int t = base >> 13;
        int l = base & 8191;
        int tci = (t * 8191) / 127;
        float tcf = (float)tci;
        __half h[4];
#pragma unroll
        for (int i = 0; i < 4; i++) {
            float x = ((float)(l + i) - tcf) / 819.2f;
            h[i] = __float2half_rn(expf(-0.5f * (x * x)));
        }
        *(uint2*)&g_Wh[base] = *(uint2*)h;
    } else if (q < nC + nW + BATCH * LL / 4) {
        int base = (q - nC - nW) * 4;
        float4 v = *(const float4*)&sig[base];
        __half h[4];
        h[0] = __float2half_rn(v.x); h[1] = __float2half_rn(v.y);
        h[2] = __float2half_rn(v.z); h[3] = __float2half_rn(v.w);
        *(uint2*)&g_sigh[base] = *(uint2*)h;
    }
}

// ---------------------------------------------------------------------------
// Persistent balanced GEMM, 2 CTAs/SM. 296 CTAs x 256 thr. CTA c owns items
// [c*4096/296, (c+1)*4096/296); item = b*128+u -> k-slab [u*64,u*64+64) of
// batch b. Warp tile 32f x 64t (8 warps). Segments (<=2) to g_part[c][seg].
// ---------------------------------------------------------------------------
__global__ void __launch_bounds__(NTH, 2)
gabor_mma() {
    extern __shared__ __align__(16) char smc[];
    const uint32_t smb = smem_u32(smc);
    const int tid = threadIdx.x, lane = tid & 31, wid = tid >> 5;
    const int c = blockIdx.x;
    const int start = c * NITEMS / NCTA;
    const int end   = (c + 1) * NITEMS / NCTA;
    const int bfirst = start >> 7;

    auto copyA = [&](int item, int buf) {
        const int u = item & 127;
        const char* src = (const char*)g_C + (size_t)u * 16384;
        const uint32_t dh = smb + OFF_A(buf);
#pragma unroll
        for (int r = 0; r < 4; r++) {
            int j = tid + NTH * r;               // 0..1023 16B chunks
            uint32_t doff = (uint32_t)(j >> 3) * ROWB + (j & 7) * 16;
            cpa16(dh + doff, src + j * 16);
        }
    };

    const int tp = tid >> 1, qq = tid & 1;       // row t, half (32 halfs each)
    auto buildP = [&](int item, int buf) {
        const int b = item >> 7, u = item & 127;
        const uint4* wp = (const uint4*)(g_Wh + (size_t)tp * LL + u * 64 + qq * 32);
        const uint4* sp = (const uint4*)(g_sigh + (size_t)b * LL + u * 64 + qq * 32);
        char* ph = smc + OFF_B(buf) + tp * ROWB + qq * 64;
#pragma unroll
        for (int m = 0; m < 4; m++) {
            uint4 w = wp[m], s = sp[m], p;
            p.x = hm2(w.x, s.x); p.y = hm2(w.y, s.y);
            p.z = hm2(w.z, s.z); p.w = hm2(w.w, s.w);
            *(uint4*)(ph + 16 * m) = p;
        }
    };

    copyA(start, 0); CP_COMMIT();
    buildP(start, 0);

    float acc[2][8][4];
#pragma unroll
    for (int m = 0; m < 2; m++)
#pragma unroll
        for (int n = 0; n < 8; n++)
#pragma unroll
            for (int q = 0; q < 4; q++) acc[m][n][q] = 0.0f;

    const int f0 = (wid & 3) * 32, t0 = (wid >> 2) * 64;
    const uint32_t loff = (uint32_t)(lane & 15) * ROWB + (lane >> 4) * 16;
    const int r0 = lane >> 2, c0 = (lane & 3) * 2;

    for (int it = start; it < end; it++) {
        CP_WAIT0();
        __syncthreads();
        const int buf = (it - start) & 1;
        if (it + 1 < end) {
            copyA(it + 1, buf ^ 1); CP_COMMIT();
            buildP(it + 1, buf ^ 1);
        }
        const uint32_t aH = smb + OFF_A(buf) + f0 * ROWB + loff;
        const uint32_t bH = smb + OFF_B(buf) + t0 * ROWB + loff;
#pragma unroll
        for (int k16 = 0; k16 < 4; k16++) {
            const uint32_t kb = k16 * 32;
            uint32_t ah[2][4], bh[4][4];
            ldsm4(ah[0], aH + kb); ldsm4(ah[1], aH + 16 * ROWB + kb);
#pragma unroll
            for (int j = 0; j < 4; j++)
                ldsm4(bh[j], bH + j * 16 * ROWB + kb);
#pragma unroll
            for (int m = 0; m < 2; m++)
#pragma unroll
                for (int j = 0; j < 4; j++) {
                    mma16816(acc[m][2 * j],     ah[m], bh[j][0], bh[j][2]);
                    mma16816(acc[m][2 * j + 1], ah[m], bh[j][1], bh[j][3]);
                }
        }

        // segment flush when batch changes or run ends
        const int bcur = it >> 7;
        if (it + 1 == end || ((it + 1) >> 7) != bcur) {
            float* dst = g_part + ((size_t)c * 2 + (bcur - bfirst)) * (NF * NT);
#pragma unroll
            for (int m = 0; m < 2; m++)
#pragma unroll
                for (int n = 0; n < 8; n++) {
                    const int f = f0 + 16 * m + r0;
                    const int t = t0 + 16 * (n >> 1) + 8 * (n & 1) + c0;
                    *(float2*)&dst[f * NT + t]       = make_float2(acc[m][n][0], acc[m][n][1]);
                    *(float2*)&dst[(f + 8) * NT + t] = make_float2(acc[m][n][2], acc[m][n][3]);
                }
            if (it + 1 < end) {
#pragma unroll
                for (int m = 0; m < 2; m++)
#pragma unroll
                    for (int n = 0; n < 8; n++)
#pragma unroll
                        for (int q = 0; q < 4; q++) acc[m][n][q] = 0.0f;
            }
        }
    }
}

// ---------------------------------------------------------------------------
// Deterministic reduce: sum segments from candidate CTAs whose runs intersect
// batch b's item range [b*128, (b+1)*128).
// ---------------------------------------------------------------------------
__global__ void reduce_out(float* __restrict__ out) {
    int i = blockIdx.x * blockDim.x + threadIdx.x;   // float4 index
    const int n4 = BATCH * NF * NT / 4;              // 131072
    if (i >= n4) return;
    const int b = i >> 12;
    const int e = i & 4095;
    float4 a = make_float4(0.f, 0.f, 0.f, 0.f);
    int cg = (b * 37) >> 2;                          // ~ b*9.25
    int clo = cg > 1 ? cg - 2 : 0;
    int chi = cg + 11; if (chi > NCTA - 1) chi = NCTA - 1;
    for (int c = clo; c <= chi; c++) {
        int sc = c * NITEMS / NCTA, ec = (c + 1) * NITEMS / NCTA;
        if (sc < (b + 1) * 128 && ec > b * 128) {
            int seg = b - (sc >> 7);
            const float4* p = (const float4*)g_part + ((size_t)c * 2 + seg) * 4096 + e;
            float4 v = *p;
            a.x += v.x; a.y += v.y; a.z += v.z; a.w += v.w;
        }
    }
    ((float4*)out)[i] = a;
}

extern "C" void kernel_launch(void* const* d_in, const int* in_sizes, int n_in,
                              void* d_out, int out_size) {
    const float* sig = (const float*)d_in[0];
    float* out = (float*)d_out;

    int ptot = (2 * LL * 128 + BATCH * LL) / 4;
    prep_tables<<<(ptot + 255) / 256, 256>>>(sig);

    cudaFuncSetAttribute(gabor_mma, cudaFuncAttributeMaxDynamicSharedMemorySize, SMEM_DYN);
    gabor_mma<<<NCTA, NTH, SMEM_DYN>>>();

    reduce_out<<<(BATCH * NF * NT / 4 + 255) / 256, 256>>>(out);
}